// round 8
// baseline (speedup 1.0000x reference)
#include <cuda_runtime.h>
#include <math.h>

// Problem dims
#define Bb 128
#define Ss 128
#define Nn 196
#define Dd 512
#define D2 1024
#define Tt 12
#define NCH 4          // split-K chunks for comb / write GEMMs
#define N3 1536        // comb GEMM output width (w2 1024 + u 512)

// ---------------- device scratch ----------------
__device__ float g_pp  [2 * Bb * Tt * Dd];   // p partials (z=2)
__device__ float g_P2p [2 * Bb * Tt * Dd];   // P2 partials (z=2)
__device__ float g_cbp [NCH * Bb * N3];      // comb GEMM partials [z][b][1536]
__device__ float g_fpA [NCH * Bb * D2];      // write partials ping
__device__ float g_fpB [NCH * Bb * D2];      // write partials pong
__device__ float g_Wcomb[N3 * Dd];           // [Wra*Wrc^T ; Wcq1]  [1536,512]
__device__ float g_Bcomb[D2 * D2];           // [Wwc ; Wrm@Wwc]     [1024,1024]
__device__ float g_bp2 [Tt * Dd];            // bp @ Wcq2^T
__device__ float g_c   [Bb * Dd];
__device__ float g_m   [Bb * Dd];            // broadcast m0
__device__ float g_mm  [Bb * Dd];            // mm for t=0
__device__ float g_r   [Bb * Dd];
__device__ float g_bias2[Dd];                // brm + Wrm@bwc

// ---------------- helpers ----------------
__device__ __forceinline__ float warp_sum(float v) {
#pragma unroll
    for (int o = 16; o; o >>= 1) v += __shfl_xor_sync(0xffffffffu, v, o);
    return v;
}
__device__ __forceinline__ float warp_max(float v) {
#pragma unroll
    for (int o = 16; o; o >>= 1) v = fmaxf(v, __shfl_xor_sync(0xffffffffu, v, o));
    return v;
}

// ---------------- setup kernels ----------------
__global__ void init_state(const float* __restrict__ ctrl0, const float* __restrict__ mem0) {
    int i = blockIdx.x * blockDim.x + threadIdx.x;
    int d = i & (Dd - 1);
    g_c[i] = ctrl0[d];
    g_m[i] = mem0[d];
}

__global__ void prep_read(const float* __restrict__ Wrm, const float* __restrict__ brm,
                          const float* __restrict__ bwc, const float* __restrict__ mem0) {
    int w = (blockIdx.x * blockDim.x + threadIdx.x) >> 5;
    int lane = threadIdx.x & 31;
    const float* row = Wrm + (size_t)w * Dd;
    float s1 = 0.f, s2 = 0.f;
    for (int d = lane; d < Dd; d += 32) { float x = row[d]; s1 += x * bwc[d]; s2 += x * mem0[d]; }
    s1 = warp_sum(s1); s2 = warp_sum(s2);
    if (lane == 0) g_bias2[w] = brm[w] + s1;
    float mm0 = brm[w] + s2;
    for (int b = lane; b < Bb; b += 32) g_mm[b * Dd + w] = mm0;
}

// Wcomb rows 0..1023: Wcomb[n*512+k] = Wra[k]*Wrc[k*1024+n]  (tiled transpose)
__global__ void prep_wcomb_t(const float* __restrict__ Wrc, const float* __restrict__ Wra) {
    __shared__ float tile[32][33];
    int n0 = blockIdx.x * 32, k0 = blockIdx.y * 32;
    int tx = threadIdx.x & 31, ty = threadIdx.x >> 5;     // 8 rows
#pragma unroll
    for (int i = 0; i < 4; i++) {
        int k = k0 + ty + i * 8;
        tile[ty + i * 8][tx] = Wra[k] * Wrc[(size_t)k * D2 + n0 + tx];
    }
    __syncthreads();
#pragma unroll
    for (int i = 0; i < 4; i++) {
        int n = n0 + ty + i * 8;
        g_Wcomb[(size_t)n * Dd + k0 + tx] = tile[tx][ty + i * 8];
    }
}

// Wcomb rows 1024..1535: copy Wcq first-half columns (Wcq1)
__global__ void prep_wcomb_c(const float* __restrict__ Wcq) {
    int idx = blockIdx.x * blockDim.x + threadIdx.x;   // 0..262143
    int r = idx >> 9, k = idx & 511;
    g_Wcomb[(size_t)(D2 + r) * Dd + k] = Wcq[(size_t)r * D2 + k];
}

// bp2[t,d] = dot(bp[t,:], Wcq2[d,:])
__global__ void prep_bp2(const float* __restrict__ bp, const float* __restrict__ Wcq) {
    int gw = (blockIdx.x * blockDim.x + threadIdx.x) >> 5;   // 0..6143
    int lane = threadIdx.x & 31;
    int t = gw >> 9, d = gw & 511;
    float s = 0.f;
    for (int j = lane; j < Dd; j += 32) s += bp[t * Dd + j] * Wcq[(size_t)d * D2 + Dd + j];
    s = warp_sum(s);
    if (lane == 0) g_bp2[t * Dd + d] = s;
}

// ---------------- split-K GEMM with multi-partial A loads ----------------
// C[M,N] = concat(A0,A1)[M,K] * B^T (+bias).  B(n,k) = Bm[n*strideN + k*strideK].
// A0/A1 may themselves be split-K partial sums: aXsum partials at stride aXpstride,
// a1bias added to the A1 half. BM=64,BN=64,BK=16, 256 thr, 4x4/thread, LDS.128.
__global__ __launch_bounds__(256) void gemm_sk(
    const float* __restrict__ A0, int lda0, int K0, int a0sum, int a0pstride,
    const float* __restrict__ A1, int lda1, int a1sum, int a1pstride,
    const float* __restrict__ a1bias,
    const float* __restrict__ Bm, int strideN, int strideK,
    const float* __restrict__ bias,
    float* __restrict__ Cfin, int ldc,
    float* __restrict__ Part,
    int K)
{
    __shared__ __align__(16) float As[16][68];
    __shared__ __align__(16) float Bs[16][68];
    const int tid = threadIdx.x;
    const int ty = tid >> 4;            // 0..15
    const int tx = tid & 15;            // 0..15
    const int bm = blockIdx.y * 64;
    const int bn = blockIdx.x * 64;
    const int N  = gridDim.x * 64;
    const int kchunk = K / gridDim.z;
    const int kbeg = blockIdx.z * kchunk;
    const int kend = kbeg + kchunk;

    const int aRow = tid >> 2, aKq = tid & 3;
    const int bKk = tid >> 4, bNx = tid & 15;
    const bool nt = (strideK == 1);

    float acc[4][4] = {};
    float4 ra, rb;

    auto loadA = [&](int gk) -> float4 {
        float4 v;
        if (gk < K0) {
            const float* s = A0 + (size_t)(bm + aRow) * lda0 + gk;
            v = *(const float4*)s;
            for (int z = 1; z < a0sum; z++) {
                float4 x = *(const float4*)(s + (size_t)z * a0pstride);
                v.x += x.x; v.y += x.y; v.z += x.z; v.w += x.w;
            }
        } else {
            int g2 = gk - K0;
            const float* s = A1 + (size_t)(bm + aRow) * lda1 + g2;
            v = *(const float4*)s;
            for (int z = 1; z < a1sum; z++) {
                float4 x = *(const float4*)(s + (size_t)z * a1pstride);
                v.x += x.x; v.y += x.y; v.z += x.z; v.w += x.w;
            }
            if (a1bias) {
                float4 bb = *(const float4*)(a1bias + g2);
                v.x += bb.x; v.y += bb.y; v.z += bb.z; v.w += bb.w;
            }
        }
        return v;
    };

    // prologue
    ra = loadA(kbeg + aKq * 4);
    if (nt)  rb = *(const float4*)(Bm + (size_t)(bn + aRow) * strideN + kbeg + aKq * 4);
    else     rb = *(const float4*)(Bm + (size_t)(kbeg + bKk) * strideK + bn + bNx * 4);

    for (int k0 = kbeg; k0 < kend; k0 += 16) {
        As[aKq * 4 + 0][aRow] = ra.x;
        As[aKq * 4 + 1][aRow] = ra.y;
        As[aKq * 4 + 2][aRow] = ra.z;
        As[aKq * 4 + 3][aRow] = ra.w;
        if (nt) {
            Bs[aKq * 4 + 0][aRow] = rb.x;
            Bs[aKq * 4 + 1][aRow] = rb.y;
            Bs[aKq * 4 + 2][aRow] = rb.z;
            Bs[aKq * 4 + 3][aRow] = rb.w;
        } else {
            *(float4*)&Bs[bKk][bNx * 4] = rb;
        }
        __syncthreads();

        if (k0 + 16 < kend) {
            int kn = k0 + 16;
            ra = loadA(kn + aKq * 4);
            if (nt)  rb = *(const float4*)(Bm + (size_t)(bn + aRow) * strideN + kn + aKq * 4);
            else     rb = *(const float4*)(Bm + (size_t)(kn + bKk) * strideK + bn + bNx * 4);
        }

#pragma unroll
        for (int kk = 0; kk < 16; kk++) {
            float4 a = *(const float4*)&As[kk][ty * 4];
            float4 b = *(const float4*)&Bs[kk][tx * 4];
            float av[4] = {a.x, a.y, a.z, a.w};
            float bv[4] = {b.x, b.y, b.z, b.w};
#pragma unroll
            for (int i = 0; i < 4; i++)
#pragma unroll
                for (int j = 0; j < 4; j++) acc[i][j] += av[i] * bv[j];
        }
        __syncthreads();
    }

    if (Part) {
        size_t base = (size_t)blockIdx.z * (size_t)(gridDim.y * 64) * N;
#pragma unroll
        for (int i = 0; i < 4; i++) {
            int m = bm + ty * 4 + i;
            float4 v = make_float4(acc[i][0], acc[i][1], acc[i][2], acc[i][3]);
            *(float4*)&Part[base + (size_t)m * N + bn + tx * 4] = v;
        }
    } else {
        float4 bz = make_float4(0.f, 0.f, 0.f, 0.f);
        if (bias) bz = *(const float4*)(bias + bn + tx * 4);
#pragma unroll
        for (int i = 0; i < 4; i++) {
            int m = bm + ty * 4 + i;
            float4 v = make_float4(acc[i][0] + bz.x, acc[i][1] + bz.y,
                                   acc[i][2] + bz.z, acc[i][3] + bz.w);
            *(float4*)&Cfin[(size_t)m * ldc + bn + tx * 4] = v;
        }
    }
}

// ---------------- ctx attention (reduces comb u-half + P2 partials) -----------
__global__ void attn_ctx(const float* __restrict__ ctx, const float* __restrict__ bcq,
                         const float* __restrict__ Wca, int t) {
    __shared__ __align__(16) float us[Dd];
    __shared__ float sl[Ss];
    __shared__ float red;
    const int b = blockIdx.x;
    const int tid = threadIdx.x;
    const int lane = tid & 31, warp = tid >> 5;

    {
        int o = b * N3 + D2 + tid;                        // u half of comb output
        float v = g_cbp[o] + g_cbp[Bb * N3 + o] + g_cbp[2 * Bb * N3 + o] + g_cbp[3 * Bb * N3 + o];
        int pr = (b * Tt + t) * Dd + tid;
        v += g_P2p[pr] + g_P2p[2 * Bb * Tt * Dd / 2 + pr];   // 2 partials, stride 786432
        v += bcq[tid] + g_bp2[t * Dd + tid];
        us[tid] = v * Wca[tid];
    }
    __syncthreads();

    const float* cb = ctx + (size_t)b * Ss * Dd;
    const float4* us4 = (const float4*)us;
    for (int s = warp; s < Ss; s += 16) {
        const float4* row4 = (const float4*)(cb + (size_t)s * Dd);
        float part = 0.f;
#pragma unroll
        for (int d4 = lane; d4 < Dd / 4; d4 += 32) {
            float4 a = row4[d4], u = us4[d4];
            part += a.x * u.x + a.y * u.y + a.z * u.z + a.w * u.w;
        }
        part = warp_sum(part);
        if (lane == 0) sl[s] = part;
    }
    __syncthreads();
    if (warp == 0) {
        float mx = -1e30f;
        for (int i = lane; i < Ss; i += 32) mx = fmaxf(mx, sl[i]);
        mx = warp_max(mx);
        float sm = 0.f;
        for (int i = lane; i < Ss; i += 32) { float e = __expf(sl[i] - mx); sl[i] = e; sm += e; }
        sm = warp_sum(sm);
        if (lane == 0) red = 1.f / sm;
    }
    __syncthreads();
    const float inv = red;
    float acc = 0.f;
#pragma unroll 8
    for (int s = 0; s < Ss; s++) acc += sl[s] * cb[(size_t)s * Dd + tid];
    g_c[b * Dd + tid] = acc * inv;
}

// ---------------- k attention (reduces comb w2-half; mm from fp or g_mm) ------
__global__ void attn_k(const float* __restrict__ kp, const float* __restrict__ fpm) {
    __shared__ float gs[Dd];
    __shared__ float rw[Nn];
    __shared__ float rw1[Nn];
    __shared__ float red;
    const int b = blockIdx.x;
    const int tid = threadIdx.x;
    const int lane = tid & 31, warp = tid >> 5;

    {
        int oa = b * N3 + tid;
        int ob = oa + Dd;
        float w2a = g_cbp[oa] + g_cbp[Bb * N3 + oa] + g_cbp[2 * Bb * N3 + oa] + g_cbp[3 * Bb * N3 + oa];
        float w2b = g_cbp[ob] + g_cbp[Bb * N3 + ob] + g_cbp[2 * Bb * N3 + ob] + g_cbp[3 * Bb * N3 + ob];
        float mmv;
        if (fpm) {
            int o = b * D2 + Dd + tid;
            mmv = fpm[o] + fpm[Bb * D2 + o] + fpm[2 * Bb * D2 + o] + fpm[3 * Bb * D2 + o]
                + g_bias2[tid];
        } else {
            mmv = g_mm[b * Dd + tid];
        }
        gs[tid] = w2a * mmv + w2b;
    }
    __syncthreads();

    const float* kb = kp + (size_t)b * Dd * Nn;
    {
        int half = tid >> 8;                 // 0 or 1
        int n = tid & 255;
        if (n < Nn) {
            float acc = 0.f;
            int j0 = half * 256;
#pragma unroll 8
            for (int j = j0; j < j0 + 256; j++) acc += gs[j] * kb[(size_t)j * Nn + n];
            (half ? rw1 : rw)[n] = acc;
        }
    }
    __syncthreads();
    if (tid < Nn) rw[tid] += rw1[tid];
    __syncthreads();
    if (warp == 0) {
        float mx = -1e30f;
        for (int i = lane; i < Nn; i += 32) mx = fmaxf(mx, rw[i]);
        mx = warp_max(mx);
        float sm = 0.f;
        for (int i = lane; i < Nn; i += 32) { float e = __expf(rw[i] - mx); rw[i] = e; sm += e; }
        sm = warp_sum(sm);
        if (lane == 0) red = 1.f / sm;
    }
    __syncthreads();
    const float inv = red;
    for (int d = warp; d < Dd; d += 16) {
        const float* row = kb + (size_t)d * Nn;
        float part = 0.f;
        for (int n = lane; n < Nn; n += 32) part += rw[n] * row[n];
        part = warp_sum(part);
        if (lane == 0) g_r[b * Dd + d] = part * inv;
    }
}

// ---------------- final output reduce ----------------
__global__ void reduce_out(const float* __restrict__ fpL, const float* __restrict__ bwc,
                           float* __restrict__ out) {
    int idx = blockIdx.x * blockDim.x + threadIdx.x;   // 0..65535
    int b = idx >> 9, j = idx & 511;
    int o = b * D2 + j;
    out[idx] = fpL[o] + fpL[Bb * D2 + o] + fpL[2 * Bb * D2 + o] + fpL[3 * Bb * D2 + o] + bwc[j];
}

// ---------------- host ----------------
extern "C" void kernel_launch(void* const* d_in, const int* in_sizes, int n_in,
                              void* d_out, int out_size)
{
    const float* ctx  = (const float*)d_in[0];
    const float* q    = (const float*)d_in[1];
    const float* kten = (const float*)d_in[2];
    const float* mem0 = (const float*)d_in[3];
    const float* ctrl0= (const float*)d_in[4];
    const float* Wp   = (const float*)d_in[5];
    const float* bp   = (const float*)d_in[6];
    const float* Wcq  = (const float*)d_in[7];
    const float* bcq  = (const float*)d_in[8];
    const float* Wca  = (const float*)d_in[9];
    const float* Wrm  = (const float*)d_in[11];
    const float* brm  = (const float*)d_in[12];
    const float* Wrc  = (const float*)d_in[13];
    const float* Wra  = (const float*)d_in[15];
    const float* Wwc  = (const float*)d_in[17];
    const float* bwc  = (const float*)d_in[18];
    float* out = (float*)d_out;

    float *pp_, *P2p_, *cbp_, *fpA_, *fpB_, *Wc_, *Bc_, *c_, *m_, *r_;
    cudaGetSymbolAddress((void**)&pp_,  g_pp);
    cudaGetSymbolAddress((void**)&P2p_, g_P2p);
    cudaGetSymbolAddress((void**)&cbp_, g_cbp);
    cudaGetSymbolAddress((void**)&fpA_, g_fpA);
    cudaGetSymbolAddress((void**)&fpB_, g_fpB);
    cudaGetSymbolAddress((void**)&Wc_,  g_Wcomb);
    cudaGetSymbolAddress((void**)&Bc_,  g_Bcomb);
    cudaGetSymbolAddress((void**)&c_,   g_c);
    cudaGetSymbolAddress((void**)&m_,   g_m);
    cudaGetSymbolAddress((void**)&r_,   g_r);

    // --- setup ---
    init_state<<<(Bb * Dd) / 256, 256>>>(ctrl0, mem0);
    prep_read<<<64, 256>>>(Wrm, brm, bwc, mem0);
    prep_wcomb_t<<<dim3(32, 16), 256>>>(Wrc, Wra);
    prep_wcomb_c<<<1024, 256>>>(Wcq);
    prep_bp2<<<768, 256>>>(bp, Wcq);
    cudaMemcpyAsync(Bc_, Wwc, (size_t)Dd * D2 * sizeof(float), cudaMemcpyDeviceToDevice, 0);
    // Bcomb bottom = Wrm @ Wwc  (M=512, N=1024, K=512, NN)
    gemm_sk<<<dim3(16, 8, 1), 256>>>(Wrm, Dd, Dd, 1, 0, nullptr, 0, 1, 0, nullptr,
                                     Wwc, 1, D2, nullptr,
                                     Bc_ + (size_t)Dd * D2, D2, nullptr, Dd);
    // p partials: q @ Wp^T  (M=128, N=6144, K=1024, z=2)
    gemm_sk<<<dim3(96, 2, 2), 256>>>(q, D2, D2, 1, 0, nullptr, 0, 1, 0, nullptr,
                                     Wp, D2, 1, nullptr,
                                     nullptr, 0, pp_, D2);
    // P2 partials: p(sum2, viewed [1536,512]) @ Wcq2^T  (M=1536, N=512, K=512, z=2)
    gemm_sk<<<dim3(8, 24, 2), 256>>>(pp_, Dd, Dd, 2, Bb * Tt * Dd, nullptr, 0, 1, 0, nullptr,
                                     Wcq + Dd, D2, 1, nullptr,
                                     nullptr, 0, P2p_, Dd);
    // comb on c0 -> u_0 (w2 half unused)
    gemm_sk<<<dim3(24, 2, NCH), 256>>>(c_, Dd, Dd, 1, 0, nullptr, 0, 1, 0, nullptr,
                                       Wc_, Dd, 1, nullptr,
                                       nullptr, 0, cbp_, Dd);

    for (int t = 0; t < Tt; t++) {
        const float* fp_prev = (t == 0) ? nullptr : ((t & 1) ? fpA_ : fpB_);
        float* fp_cur = (t & 1) ? fpB_ : fpA_;

        attn_ctx<<<Bb, Dd>>>(ctx, bcq, Wca, t);
        // comb: c @ Wcomb^T -> [w2_t ; u_{t+1}]  (M=128, N=1536, K=512, z=4)
        gemm_sk<<<dim3(24, 2, NCH), 256>>>(c_, Dd, Dd, 1, 0, nullptr, 0, 1, 0, nullptr,
                                           Wc_, Dd, 1, nullptr,
                                           nullptr, 0, cbp_, Dd);
        attn_k<<<Bb, Dd>>>(kten, fp_prev);
        // write: concat(r, m) @ Bcomb^T  (M=128, N=1024, K=1024, z=4)
        if (t == 0) {
            gemm_sk<<<dim3(16, 2, NCH), 256>>>(r_, Dd, Dd, 1, 0,
                                               m_, Dd, 1, 0, nullptr,
                                               Bc_, D2, 1, nullptr,
                                               nullptr, 0, fp_cur, D2);
        } else {
            gemm_sk<<<dim3(16, 2, NCH), 256>>>(r_, Dd, Dd, 1, 0,
                                               (float*)fp_prev, D2, NCH, Bb * D2, bwc,
                                               Bc_, D2, 1, nullptr,
                                               nullptr, 0, fp_cur, D2);
        }
    }
    // final m -> out  (last write went to fpB_ since Tt even -> t=11 odd -> fpB_)
    reduce_out<<<(Bb * Dd) / 256, 256>>>(fpB_, bwc, out);

    (void)in_sizes; (void)n_in; (void)out_size;
}

// round 9
// speedup vs baseline: 1.1763x; 1.1763x over previous
#include <cuda_runtime.h>
#include <math.h>

#define Bb 128
#define Ss 128
#define Nn 196
#define Dd 512
#define D2 1024
#define Tt 12
#define N3 1536

#define NB 128
#define NTH 512

#define ZP 16      // p GEMM split-K (K=1024)
#define ZB 8       // Wrm@Wwc split-K (K=512)
#define Z2 8       // P2 split-K (K=512)
#define ZC 8       // comb split-K (K=512)
#define ZW 16      // write split-K (K=1024)

// ---------------- device scratch ----------------
__device__ float g_pp   [ZP * Bb * Tt * Dd];
__device__ float g_pfull[Bb * Tt * Dd];
__device__ float g_P2p  [Z2 * Bb * Tt * Dd];
__device__ float g_cbp  [ZC * Bb * N3];
__device__ float g_fpA  [ZW * Bb * D2];
__device__ float g_fpB  [ZW * Bb * D2];
__device__ float g_BcP  [ZB * Dd * D2];
__device__ float g_BcF  [Dd * D2];
__device__ float g_bp2  [Tt * Dd];
__device__ float g_c    [Bb * Dd];
__device__ float g_m0   [Bb * Dd];
__device__ float g_mf   [Bb * Dd];
__device__ float g_r    [Bb * Dd];
__device__ float g_bias2[Dd];
__device__ float g_mmrow[Dd];

__device__ int          g_bar_count = 0;
__device__ volatile int g_bar_gen   = 0;

// ---------------- helpers ----------------
__device__ __forceinline__ float warp_sum(float v) {
#pragma unroll
    for (int o = 16; o; o >>= 1) v += __shfl_xor_sync(0xffffffffu, v, o);
    return v;
}
__device__ __forceinline__ float warp_max(float v) {
#pragma unroll
    for (int o = 16; o; o >>= 1) v = fmaxf(v, __shfl_xor_sync(0xffffffffu, v, o));
    return v;
}

// grid barrier: all NB blocks co-resident by construction
__device__ __forceinline__ void grid_sync(int& gen) {
    __syncthreads();
    if (threadIdx.x == 0) {
        __threadfence();
        if (atomicAdd(&g_bar_count, 1) == NB - 1) {
            g_bar_count = 0;
            __threadfence();
            g_bar_gen = gen + 1;
        } else {
            while ((int)(g_bar_gen - gen) <= 0) { }
        }
        __threadfence();
    }
    __syncthreads();
    gen++;
}

// ---------------- GEMM tile: C[128,256] += A[128,klen] * B^T, 512 thr --------
// B(n,k) = B[n*ldbN + k*ldbK] (+optional k-scale ks for NN path).
// Thread (ty=warp 0..15, tx=lane): rows ty*8..+7, cols {tx*4..+3, 128+tx*4..+3}.
__device__ void gemm_tile(const float* __restrict__ A, int lda,
                          const float* __restrict__ B, int ldbN, int ldbK,
                          const float* __restrict__ ks,
                          float* __restrict__ C, int ldc, int klen,
                          float* __restrict__ sh)
{
    float* As = sh;             // [16][132]
    float* Bs = sh + 16 * 132;  // [16][260]
    const int tid = threadIdx.x;
    const int ty = tid >> 5;
    const int tx = tid & 31;
    const int aRow = tid >> 2, aK4 = (tid & 3) << 2;
    const int bRow = tid >> 1, bK8 = (tid & 1) << 3;
    const int kR = tid >> 5,   nQ = tid & 31;
    const bool nt = (ldbK == 1);

    float acc[8][8];
#pragma unroll
    for (int i = 0; i < 8; i++)
#pragma unroll
        for (int j = 0; j < 8; j++) acc[i][j] = 0.f;

    float4 ra, rb0, rb1;
    ra = *(const float4*)(A + (size_t)aRow * lda + aK4);
    if (nt) {
        const float* bp_ = B + (size_t)bRow * ldbN + bK8;
        rb0 = *(const float4*)bp_;
        rb1 = *(const float4*)(bp_ + 4);
    } else {
        const float* bp_ = B + (size_t)kR * ldbK;
        rb0 = *(const float4*)(bp_ + nQ * 4);
        rb1 = *(const float4*)(bp_ + 128 + nQ * 4);
        if (ks) {
            float s = ks[kR];
            rb0.x *= s; rb0.y *= s; rb0.z *= s; rb0.w *= s;
            rb1.x *= s; rb1.y *= s; rb1.z *= s; rb1.w *= s;
        }
    }

    for (int k0 = 0; k0 < klen; k0 += 16) {
        As[(aK4 + 0) * 132 + aRow] = ra.x;
        As[(aK4 + 1) * 132 + aRow] = ra.y;
        As[(aK4 + 2) * 132 + aRow] = ra.z;
        As[(aK4 + 3) * 132 + aRow] = ra.w;
        if (nt) {
            Bs[(bK8 + 0) * 260 + bRow] = rb0.x;
            Bs[(bK8 + 1) * 260 + bRow] = rb0.y;
            Bs[(bK8 + 2) * 260 + bRow] = rb0.z;
            Bs[(bK8 + 3) * 260 + bRow] = rb0.w;
            Bs[(bK8 + 4) * 260 + bRow] = rb1.x;
            Bs[(bK8 + 5) * 260 + bRow] = rb1.y;
            Bs[(bK8 + 6) * 260 + bRow] = rb1.z;
            Bs[(bK8 + 7) * 260 + bRow] = rb1.w;
        } else {
            *(float4*)(Bs + kR * 260 + nQ * 4) = rb0;
            *(float4*)(Bs + kR * 260 + 128 + nQ * 4) = rb1;
        }
        __syncthreads();

        if (k0 + 16 < klen) {
            int kn = k0 + 16;
            ra = *(const float4*)(A + (size_t)aRow * lda + kn + aK4);
            if (nt) {
                const float* bp_ = B + (size_t)bRow * ldbN + kn + bK8;
                rb0 = *(const float4*)bp_;
                rb1 = *(const float4*)(bp_ + 4);
            } else {
                const float* bp_ = B + (size_t)(kn + kR) * ldbK;
                rb0 = *(const float4*)(bp_ + nQ * 4);
                rb1 = *(const float4*)(bp_ + 128 + nQ * 4);
                if (ks) {
                    float s = ks[kn + kR];
                    rb0.x *= s; rb0.y *= s; rb0.z *= s; rb0.w *= s;
                    rb1.x *= s; rb1.y *= s; rb1.z *= s; rb1.w *= s;
                }
            }
        }

#pragma unroll
        for (int kk = 0; kk < 16; kk++) {
            float4 a0 = *(const float4*)(As + kk * 132 + ty * 8);
            float4 a1 = *(const float4*)(As + kk * 132 + ty * 8 + 4);
            float4 b0 = *(const float4*)(Bs + kk * 260 + tx * 4);
            float4 b1 = *(const float4*)(Bs + kk * 260 + 128 + tx * 4);
            float av[8] = {a0.x, a0.y, a0.z, a0.w, a1.x, a1.y, a1.z, a1.w};
            float bv[8] = {b0.x, b0.y, b0.z, b0.w, b1.x, b1.y, b1.z, b1.w};
#pragma unroll
            for (int i = 0; i < 8; i++)
#pragma unroll
                for (int j = 0; j < 8; j++) acc[i][j] += av[i] * bv[j];
        }
        __syncthreads();
    }

#pragma unroll
    for (int i = 0; i < 8; i++) {
        int m = ty * 8 + i;
        *(float4*)(C + (size_t)m * ldc + tx * 4)       = make_float4(acc[i][0], acc[i][1], acc[i][2], acc[i][3]);
        *(float4*)(C + (size_t)m * ldc + 128 + tx * 4) = make_float4(acc[i][4], acc[i][5], acc[i][6], acc[i][7]);
    }
}

// comb job z in [0,ZC), nI in [0,6): c @ [Wra*Wrc^T ; Wcq1]^T chunk -> cbp
__device__ __forceinline__ void do_comb(int z, int nI,
                                        const float* __restrict__ Wrc,
                                        const float* __restrict__ Wra,
                                        const float* __restrict__ Wcq,
                                        float* sh)
{
    int bn = nI * 256;
    if (bn < D2) {      // w2 half: B(n,k)=Wra[k]*Wrc[k,n]  (NN + kscale)
        gemm_tile(g_c + z * 64, Dd,
                  Wrc + (size_t)(z * 64) * D2 + bn, 1, D2, Wra + z * 64,
                  g_cbp + (size_t)z * (Bb * N3) + bn, N3, 64, sh);
    } else {            // u half: B(n,k)=Wcq[n, k] (first 512 cols, NT)
        gemm_tile(g_c + z * 64, Dd,
                  Wcq + (size_t)(bn - D2) * D2 + z * 64, D2, 1, nullptr,
                  g_cbp + (size_t)z * (Bb * N3) + bn, N3, 64, sh);
    }
}

// write job j in [0,64): concat(r, m_tw) @ [Wwc ; Wrm@Wwc]^T chunk -> fp(tw)
__device__ __forceinline__ void do_write(int tw, int j,
                                         const float* __restrict__ Wwc,
                                         float* sh)
{
    int z = j >> 2, nI = j & 3;
    int kbeg = z * 64, bn = nI * 256;
    const float* A = (kbeg < Dd) ? (g_r + kbeg)
                                 : ((tw == 0 ? g_m0 : g_mf) + (kbeg - Dd));
    const float* Bp = (bn < Dd) ? (Wwc + (size_t)bn * D2 + kbeg)
                                : (g_BcF + (size_t)(bn - Dd) * D2 + kbeg);
    float* fp = (tw & 1) ? g_fpB : g_fpA;
    gemm_tile(A, Dd, Bp, D2, 1, nullptr,
              fp + (size_t)z * (Bb * D2) + bn, D2, 64, sh);
}

// ---------------- persistent mega-kernel ----------------
__global__ void __launch_bounds__(NTH, 1) mac_mega(
    const float* __restrict__ ctx, const float* __restrict__ q,
    const float* __restrict__ kten, const float* __restrict__ mem0,
    const float* __restrict__ ctrl0, const float* __restrict__ Wp,
    const float* __restrict__ bp, const float* __restrict__ Wcq,
    const float* __restrict__ bcq, const float* __restrict__ Wca,
    const float* __restrict__ Wrm, const float* __restrict__ brm,
    const float* __restrict__ Wrc, const float* __restrict__ Wra,
    const float* __restrict__ Wwc, const float* __restrict__ bwc,
    float* __restrict__ out)
{
    __shared__ __align__(16) float sh[16 * 132 + 16 * 260];
    __shared__ __align__(16) float us[Dd];
    __shared__ float sl[Ss];
    __shared__ float rw0[256];
    __shared__ float rw1[256];
    __shared__ float red;

    const int bid = blockIdx.x;
    const int tid = threadIdx.x;
    const int lane = tid & 31, wrp = tid >> 5;
    int gen = g_bar_gen;

    // ===== S1: init states + small dots + p GEMM + Wrm@Wwc partials =====
    {
        int i = bid * NTH + tid;                       // Bb*Dd threads exactly
        g_c[i]  = ctrl0[i & (Dd - 1)];
        g_m0[i] = mem0[i & (Dd - 1)];
    }
    for (int job = bid * 16 + wrp; job < 512 + Tt * Dd; job += NB * 16) {
        if (job < 512) {
            int d = job;
            const float* row = Wrm + (size_t)d * Dd;
            float s1 = 0.f, s2 = 0.f;
            for (int j = lane; j < Dd; j += 32) { float x = row[j]; s1 += x * bwc[j]; s2 += x * mem0[j]; }
            s1 = warp_sum(s1); s2 = warp_sum(s2);
            if (lane == 0) { g_bias2[d] = brm[d] + s1; g_mmrow[d] = brm[d] + s2; }
        } else {
            int idx = job - 512; int t = idx >> 9, d = idx & 511;
            float s = 0.f;
            for (int j = lane; j < Dd; j += 32) s += bp[t * Dd + j] * Wcq[(size_t)d * D2 + Dd + j];
            s = warp_sum(s);
            if (lane == 0) g_bp2[t * Dd + d] = s;
        }
    }
    for (int j = bid; j < 384 + 128; j += NB) {
        if (j < 384) {
            // p partials: q[128,1024] @ Wp[6144,1024]^T  (24 nI x 16 z)
            int z = j / 24, nI = j % 24;
            gemm_tile(q + z * 64, D2,
                      Wp + (size_t)(nI * 256) * D2 + z * 64, D2, 1, nullptr,
                      g_pp + (size_t)z * (Bb * Tt * Dd) + nI * 256, Tt * Dd, 64, sh);
        } else {
            // BcBot partials: Wrm[512,512] @ Wwc (NN)  (8z x 4m x 4n)
            int r = j - 384; int z = r >> 4, mI = (r >> 2) & 3, nI = r & 3;
            gemm_tile(Wrm + (size_t)(mI * 128) * Dd + z * 64, Dd,
                      Wwc + (size_t)(z * 64) * D2 + nI * 256, 1, D2, nullptr,
                      g_BcP + (size_t)z * (Dd * D2) + (size_t)(mI * 128) * D2 + nI * 256,
                      D2, 64, sh);
        }
    }
    grid_sync(gen);

    // ===== S1.5: reduce p and BcBot partials =====
    {
        const int tot = Bb * Tt * Dd;
        for (int i = bid * NTH + tid; i < tot; i += NB * NTH) {
            float v = 0.f;
#pragma unroll
            for (int z = 0; z < ZP; z++) v += g_pp[(size_t)z * tot + i];
            g_pfull[i] = v;
        }
        const int tot2 = Dd * D2;
        for (int i = bid * NTH + tid; i < tot2; i += NB * NTH) {
            float v = 0.f;
#pragma unroll
            for (int z = 0; z < ZB; z++) v += g_BcP[(size_t)z * tot2 + i];
            g_BcF[i] = v;
        }
    }
    grid_sync(gen);

    // ===== S2: P2 GEMM partials + comb(c0) =====
    for (int j = bid; j < 192 + 48; j += NB) {
        if (j < 192) {
            // P2: pfull[1536,512] @ Wcq2[512,512]^T  (8z x 12m x 2n)
            int z = j / 24, r = j % 24, mI = r >> 1, nI = r & 1;
            gemm_tile(g_pfull + (size_t)(mI * 128) * Dd + z * 64, Dd,
                      Wcq + (size_t)(nI * 256) * D2 + Dd + z * 64, D2, 1, nullptr,
                      g_P2p + (size_t)z * (Bb * Tt * Dd) + (size_t)(mI * 128) * Dd + nI * 256,
                      Dd, 64, sh);
        } else {
            int r = j - 192;
            do_comb(r / 6, r % 6, Wrc, Wra, Wcq, sh);
        }
    }
    grid_sync(gen);

    // ===== main loop =====
    for (int t = 0; t < Tt; t++) {
        // ---- P1: attn_ctx(t), block = batch ----
        {
            const int b = bid, d = tid;
            float v = 0.f;
#pragma unroll
            for (int z = 0; z < ZC; z++) v += g_cbp[(size_t)z * (Bb * N3) + b * N3 + D2 + d];
            float v2 = 0.f;
#pragma unroll
            for (int z = 0; z < Z2; z++) v2 += g_P2p[(size_t)z * (Bb * Tt * Dd) + (b * Tt + t) * Dd + d];
            v += v2 + bcq[d] + g_bp2[t * Dd + d];
            us[d] = v * Wca[d];
            __syncthreads();

            const float* cb = ctx + (size_t)b * Ss * Dd;
            const float4* us4 = (const float4*)us;
            for (int s = wrp; s < Ss; s += 16) {
                const float4* row4 = (const float4*)(cb + (size_t)s * Dd);
                float part = 0.f;
#pragma unroll
                for (int d4 = lane; d4 < Dd / 4; d4 += 32) {
                    float4 a = row4[d4], u = us4[d4];
                    part += a.x * u.x + a.y * u.y + a.z * u.z + a.w * u.w;
                }
                part = warp_sum(part);
                if (lane == 0) sl[s] = part;
            }
            __syncthreads();
            if (wrp == 0) {
                float mx = -1e30f;
                for (int i = lane; i < Ss; i += 32) mx = fmaxf(mx, sl[i]);
                mx = warp_max(mx);
                float sm = 0.f;
                for (int i = lane; i < Ss; i += 32) { float e = __expf(sl[i] - mx); sl[i] = e; sm += e; }
                sm = warp_sum(sm);
                if (lane == 0) red = 1.f / sm;
            }
            __syncthreads();
            const float inv = red;
            float a = 0.f;
#pragma unroll 8
            for (int s = 0; s < Ss; s++) a += sl[s] * cb[(size_t)s * Dd + d];
            g_c[b * Dd + d] = a * inv;
        }
        grid_sync(gen);

        // ---- P2: comb(t) 48 jobs + write(t-1) 64 jobs ----
        {
            int njobs = (t > 0) ? 112 : 48;
            for (int j = bid; j < njobs; j += NB) {
                if (j < 48) do_comb(j / 6, j % 6, Wrc, Wra, Wcq, sh);
                else        do_write(t - 1, j - 48, Wwc, sh);
            }
        }
        grid_sync(gen);

        // ---- P3: attn_k(t), block = batch; also reduce m_t -> g_mf ----
        {
            const int b = bid, d = tid;
            float w2a = 0.f, w2b = 0.f;
#pragma unroll
            for (int z = 0; z < ZC; z++) {
                w2a += g_cbp[(size_t)z * (Bb * N3) + b * N3 + d];
                w2b += g_cbp[(size_t)z * (Bb * N3) + b * N3 + Dd + d];
            }
            float mmv;
            if (t == 0) {
                mmv = g_mmrow[d];
            } else {
                const float* fp = ((t - 1) & 1) ? g_fpB : g_fpA;
                float s1 = 0.f, mval = 0.f;
#pragma unroll
                for (int z = 0; z < ZW; z++) {
                    s1   += fp[(size_t)z * (Bb * D2) + b * D2 + Dd + d];
                    mval += fp[(size_t)z * (Bb * D2) + b * D2 + d];
                }
                mmv = s1 + g_bias2[d];
                g_mf[b * Dd + d] = mval + bwc[d];
            }
            us[d] = w2a * mmv + w2b;
            __syncthreads();

            const float* kb = kten + (size_t)b * Dd * Nn;
            {
                int half = tid >> 8, n = tid & 255;
                if (n < Nn) {
                    float acc = 0.f;
                    int j0 = half * 256;
#pragma unroll 8
                    for (int j2 = j0; j2 < j0 + 256; j2++) acc += us[j2] * kb[(size_t)j2 * Nn + n];
                    (half ? rw1 : rw0)[n] = acc;
                }
            }
            __syncthreads();
            if (tid < Nn) rw0[tid] += rw1[tid];
            __syncthreads();
            if (wrp == 0) {
                float mx = -1e30f;
                for (int i = lane; i < Nn; i += 32) mx = fmaxf(mx, rw0[i]);
                mx = warp_max(mx);
                float sm = 0.f;
                for (int i = lane; i < Nn; i += 32) { float e = __expf(rw0[i] - mx); rw0[i] = e; sm += e; }
                sm = warp_sum(sm);
                if (lane == 0) red = 1.f / sm;
            }
            __syncthreads();
            const float inv = red;
            for (int dd2 = wrp; dd2 < Dd; dd2 += 16) {
                const float* row = kb + (size_t)dd2 * Nn;
                float part = 0.f;
                for (int n = lane; n < Nn; n += 32) part += rw0[n] * row[n];
                part = warp_sum(part);
                if (lane == 0) g_r[b * Dd + dd2] = part * inv;
            }
        }
        grid_sync(gen);
    }

    // ===== final: write(11) then reduce to out =====
    for (int j = bid; j < 64; j += NB) do_write(Tt - 1, j, Wwc, sh);
    grid_sync(gen);
    {
        // Tt-1 = 11 odd -> fpB holds last write partials
        float v = 0.f;
#pragma unroll
        for (int z = 0; z < ZW; z++) v += g_fpB[(size_t)z * (Bb * D2) + bid * D2 + tid];
        out[bid * Dd + tid] = v + bwc[tid];
    }
}

// ---------------- host ----------------
extern "C" void kernel_launch(void* const* d_in, const int* in_sizes, int n_in,
                              void* d_out, int out_size)
{
    const float* ctx  = (const float*)d_in[0];
    const float* q    = (const float*)d_in[1];
    const float* kten = (const float*)d_in[2];
    const float* mem0 = (const float*)d_in[3];
    const float* ctrl0= (const float*)d_in[4];
    const float* Wp   = (const float*)d_in[5];
    const float* bp   = (const float*)d_in[6];
    const float* Wcq  = (const float*)d_in[7];
    const float* bcq  = (const float*)d_in[8];
    const float* Wca  = (const float*)d_in[9];
    const float* Wrm  = (const float*)d_in[11];
    const float* brm  = (const float*)d_in[12];
    const float* Wrc  = (const float*)d_in[13];
    const float* Wra  = (const float*)d_in[15];
    const float* Wwc  = (const float*)d_in[17];
    const float* bwc  = (const float*)d_in[18];
    float* out = (float*)d_out;

    mac_mega<<<NB, NTH>>>(ctx, q, kten, mem0, ctrl0, Wp, bp, Wcq, bcq, Wca,
                          Wrm, brm, Wrc, Wra, Wwc, bwc, out);

    (void)in_sizes; (void)n_in; (void)out_size;
}